// round 17
// baseline (speedup 1.0000x reference)
#include <cuda_runtime.h>

// Vanilla tanh RNN: B=512, S=4096, H=40, fp32.
// out = concat( [B*S] per-step fc outputs , [B*H] final hidden )
//
// R17 = R15 (barrier-free, branch-free, predicated stores; best 363us)
// + scheduling polish:
//  - lane-8 fc output via pointer-bump predicated STG (no per-step IMAD/SEL)
//  - each step's prep (x shuffle + init FMAs) sits between the previous
//    step's STSes and this step's LDS batch -> balanced store->load spacing
//    on BOTH parities (R16 showed too-close LDS replays; R15 had one parity
//    tighter than the other)
//  - c-dot fma2 issues first in the interleave (its tail feeds the last-read
//    slots 32..39 of the next step's LDS)
// One warp per batch, one warp per CTA (512 x 32). In-order LSU guarantees
// LDS-after-STS correctness without barriers; all conditional stores are
// SASS @p predicated (no divergence, no BSSY/BSYNC in the loop).
// tanh = single MUFU tanh.approx. Lane 8 stores fc z one step behind.

#define BATCH 512
#define SEQ   4096
#define HID   40
#define KCH   64
#define THREADS 32
#define FULLM 0xffffffffu

typedef unsigned long long u64;

__device__ __forceinline__ u64 pack2(float lo, float hi) {
    u64 r;
    asm("mov.b64 %0, {%1, %2};" : "=l"(r) : "f"(lo), "f"(hi));
    return r;
}
__device__ __forceinline__ void unpack2(u64 v, float& lo, float& hi) {
    asm("mov.b64 {%0, %1}, %2;" : "=f"(lo), "=f"(hi) : "l"(v));
}
__device__ __forceinline__ u64 fma2(u64 a, u64 b, u64 c) {
    u64 d;
    asm("fma.rn.f32x2 %0, %1, %2, %3;" : "=l"(d) : "l"(a), "l"(b), "l"(c));
    return d;
}
__device__ __forceinline__ void lds2(u64& a, u64& b, unsigned off) {
    asm volatile("ld.shared.v2.u64 {%0, %1}, [%2];"
                 : "=l"(a), "=l"(b) : "r"(off) : "memory");
}
__device__ __forceinline__ void sts1(unsigned off, float v) {
    asm volatile("st.shared.f32 [%0], %1;" :: "r"(off), "f"(v) : "memory");
}
// predicated shared store (no branch)
__device__ __forceinline__ void sts1_pred(unsigned off, float v, int pred) {
    asm volatile(
        "{\n\t"
        ".reg .pred p;\n\t"
        "setp.ne.s32 p, %2, 0;\n\t"
        "@p st.shared.f32 [%0], %1;\n\t"
        "}"
        :: "r"(off), "f"(v), "r"(pred) : "memory");
}
// predicated global store (no branch)
__device__ __forceinline__ void stg_pred(float* ptr, float v, int pred) {
    asm volatile(
        "{\n\t"
        ".reg .pred p;\n\t"
        "setp.ne.s32 p, %2, 0;\n\t"
        "@p st.global.f32 [%0], %1;\n\t"
        "}"
        :: "l"(ptr), "f"(v), "r"(pred) : "memory");
}
__device__ __forceinline__ float tanh_mufu(float z) {
    float r;
    asm("tanh.approx.f32 %0, %1;" : "=f"(r) : "f"(z));
    return r;
}

struct Lane {
    u64 wm[HID / 2], wx[HID / 2];
    float wih_m, cb_m, wih_x, cb_x;
};

// one recurrence step; accumulator inits precomputed (spacing after stores).
// c-dot leads the interleave so its tail (slots 32..39) lands earlier.
__device__ __forceinline__ float rnn_step(
    unsigned rd, unsigned wr, float ia, float ic, int l, int is_low8,
    const Lane& W, float& hm, float& hxv)
{
    u64 hp[HID / 2];
#pragma unroll
    for (int q = 0; q < HID / 4; q++)
        lds2(hp[2 * q], hp[2 * q + 1], rd + 16u * q);

    u64 a0 = pack2(ia, 0.0f);
    u64 c0 = pack2(ic, 0.0f);
#pragma unroll
    for (int j = 0; j < HID / 2; j++) {
        c0 = fma2(W.wx[j], hp[j], c0);
        a0 = fma2(W.wm[j], hp[j], a0);
    }
    float clo, chi, alo, ahi;
    unpack2(c0, clo, chi);
    float zc = clo + chi;              // lane>=8: fc_w . h_{t-1} + fc_b
    hxv = tanh_mufu(zc);
    sts1_pred(wr + 4u * (32 + l), hxv, is_low8);

    unpack2(a0, alo, ahi);
    hm = tanh_mufu(alo + ahi);
    sts1(wr + 4u * l, hm);
    return zc;
}

__global__ void __launch_bounds__(THREADS, 8) rnn_kernel(
    const float* __restrict__ x,       // [B, S]
    const float* __restrict__ hidden,  // [B, H]
    const float* __restrict__ w_ih,    // [H]
    const float* __restrict__ w_hh,    // [H, H]
    const float* __restrict__ b_ih,    // [H]
    const float* __restrict__ b_hh,    // [H]
    const float* __restrict__ fc_w,    // [H]
    const float* __restrict__ fc_b,    // [1]
    float* __restrict__ out)           // [B*S] then [B*H]
{
    __shared__ __align__(16) float buf[2][HID];

    const int l  = threadIdx.x;        // one warp per CTA
    const int bg = blockIdx.x;
    const int is_low8 = (l < 8) ? 1 : 0;
    const int is_l8   = (l == 8) ? 1 : 0;

    Lane W;
#pragma unroll
    for (int j = 0; j < HID / 2; j++)
        W.wm[j] = pack2(w_hh[l * HID + 2 * j], w_hh[l * HID + 2 * j + 1]);

    const float* row2;
    if (l < 8) {
        row2 = &w_hh[(32 + l) * HID];
        W.wih_x = w_ih[32 + l];
        W.cb_x  = b_ih[32 + l] + b_hh[32 + l];
    } else {
        row2 = fc_w;
        W.wih_x = 0.0f;
        W.cb_x  = fc_b[0];
    }
#pragma unroll
    for (int j = 0; j < HID / 2; j++)
        W.wx[j] = pack2(row2[2 * j], row2[2 * j + 1]);

    W.wih_m = w_ih[l];
    W.cb_m  = b_ih[l] + b_hh[l];

    // initial state -> buf0
    float hm = hidden[bg * HID + l];
    float hxv = 0.0f;
    buf[0][l] = hm;
    if (l < 8) {
        hxv = hidden[bg * HID + 32 + l];
        buf[0][32 + l] = hxv;
    }
    __syncthreads();

    const unsigned off0 = (unsigned)__cvta_generic_to_shared(&buf[0][0]);
    const unsigned off1 = (unsigned)__cvta_generic_to_shared(&buf[1][0]);

    // pointer-bump output stream for lane 8: step t (t>=1) writes out[t-1].
    // Start at out[bg*SEQ - 1]; bump before use at t=0 writes out[-1+1]=out[0]
    // twice (t=0 dummy then t=1 real) -- handled by starting the bump so the
    // t=0 value lands on out[0] and t=1 overwrites it (same-thread order).
    float* outp = out + bg * SEQ;      // next predicated store target

    float xa = x[bg * SEQ + l];
    float xb = x[bg * SEQ + 32 + l];

    for (int chunk = 0; chunk < SEQ / KCH; chunk++) {
        const int t0n = ((chunk + 1) % (SEQ / KCH)) * KCH;
        float xan = x[bg * SEQ + t0n + l];
        float xbn = x[bg * SEQ + t0n + 32 + l];

#pragma unroll 4
        for (int k = 0; k < KCH; k += 2) {
            // prep0 (spacing after previous step's stores)
            float xv0 = __shfl_sync(FULLM, (k & 32) ? xb : xa, k & 31);
            float ia0 = fmaf(xv0, W.wih_m, W.cb_m);
            float ic0 = fmaf(xv0, W.wih_x, W.cb_x);

            // even step: read buf0, write buf1
            float zc0 = rnn_step(off0, off1, ia0, ic0, l, is_low8, W, hm, hxv);

            // prep1 (spacing after step0's stores, before step1's LDS)
            float xv1 = __shfl_sync(FULLM, ((k + 1) & 32) ? xb : xa, (k + 1) & 31);
            float ia1 = fmaf(xv1, W.wih_m, W.cb_m);
            float ic1 = fmaf(xv1, W.wih_x, W.cb_x);
            // step0 output: first loop trip writes out[0] (dummy slot),
            // overwritten by the next store (in-order same thread)
            stg_pred(outp, zc0, is_l8);

            // odd step: read buf1, write buf0
            float zc1 = rnn_step(off1, off0, ia1, ic1, l, is_low8, W, hm, hxv);
            // bump only when this isn't the global first pair's first store:
            // t=0's zc is meaningless; both first stores target out[0] and
            // t=1's (zc1 of first pair) is the real out[0].
            outp += (chunk | k) ? 1 : 0;
            stg_pred(outp, zc1, is_l8);
            outp += 1;
        }

        xa = xan;
        xb = xbn;
    }

    // ---- epilogue: out[S-1] = fc . h_{S-1} + fc_b (h is in buf0, SEQ even) ----
    __syncthreads();
    if (l == 8) {
        u64 hp[HID / 2];
#pragma unroll
        for (int q = 0; q < HID / 4; q++)
            lds2(hp[2 * q], hp[2 * q + 1], off0 + 16u * q);
        u64 c0 = pack2(W.cb_x, 0.0f);
#pragma unroll
        for (int j = 0; j < HID / 2; j++)
            c0 = fma2(W.wx[j], hp[j], c0);
        float clo, chi;
        unpack2(c0, clo, chi);
        out[bg * SEQ + SEQ - 1] = clo + chi;
    }

    // ---- final hidden ----
    out[BATCH * SEQ + bg * HID + l] = hm;
    if (l < 8) out[BATCH * SEQ + bg * HID + 32 + l] = hxv;
}

extern "C" void kernel_launch(void* const* d_in, const int* in_sizes, int n_in,
                              void* d_out, int out_size) {
    const float* x      = (const float*)d_in[0];
    const float* hidden = (const float*)d_in[1];
    const float* w_ih   = (const float*)d_in[2];
    const float* w_hh   = (const float*)d_in[3];
    const float* b_ih   = (const float*)d_in[4];
    const float* b_hh   = (const float*)d_in[5];
    const float* fc_w   = (const float*)d_in[6];
    const float* fc_b   = (const float*)d_in[7];
    float* out = (float*)d_out;

    rnn_kernel<<<BATCH, THREADS>>>(x, hidden, w_ih, w_hh, b_ih, b_hh,
                                   fc_w, fc_b, out);
}